// round 8
// baseline (speedup 1.0000x reference)
#include <cuda_runtime.h>
#include <cuda_bf16.h>

#define C 4096

#define NBAND 8
#define MV3_BLOCKS 3072            // 8 bands * 384  (384 = 64 rowgrp * 2 kc * 3 mat)
#define WKV_BLOCKS 8
#define OW_BLOCKS  4096            // 8 kc * 512 rowgrp
#define RED_BLOCKS 16
#define TOTAL_BLOCKS (MV3_BLOCKS + WKV_BLOCKS + OW_BLOCKS + RED_BLOCKS)

// Scratch (allocation-free rule: __device__ globals)
__device__ float g_x3[3 * C];          // xk | xv | xr
__device__ float g_kvr_p[2][3 * C];    // matvec3 partials per K-chunk
__device__ float g_rwkv[C];            // r * wkv
__device__ float g_owp[8][C];          // ow partials per K-chunk

// Pipeline state (zero-init; reset by reducer 15 each launch)
__device__ unsigned g_mix_ctr;
__device__ unsigned g_band_ctr[NBAND];
__device__ unsigned g_rwkv_flag[NBAND];
__device__ unsigned g_rowred_ctr[RED_BLOCKS];
__device__ unsigned g_red_done;

__device__ __forceinline__ void block_signal(unsigned* p) {
    __threadfence();
    __syncthreads();
    if (threadIdx.x == 0) atomicAdd(p, 1u);
}

__device__ __forceinline__ void block_wait(unsigned* p, unsigned target) {
    if (threadIdx.x == 0) {
        while (*(volatile unsigned*)p < target) __nanosleep(128);
    }
    __syncthreads();
    __threadfence();
}

__device__ __forceinline__ void l2_prefetch(const void* p) {
    asm volatile("prefetch.global.L2 [%0];" :: "l"(p));
}

// Partial dot: CHUNK4 float4 per lane. W streamed (__ldcs), x read-only path.
template <int CHUNK4>
__device__ __forceinline__ float partial_dot(const float4* __restrict__ Wr,
                                             const float4* __restrict__ xv,
                                             int lane) {
    float4 a0 = make_float4(0.f, 0.f, 0.f, 0.f);
    float4 a1 = make_float4(0.f, 0.f, 0.f, 0.f);
#pragma unroll
    for (int j = 0; j < CHUNK4; j += 2) {
        float4 w0 = __ldcs(&Wr[lane + (j + 0) * 32]);
        float4 w1 = __ldcs(&Wr[lane + (j + 1) * 32]);
        float4 x0 = __ldg(&xv[lane + (j + 0) * 32]);
        float4 x1 = __ldg(&xv[lane + (j + 1) * 32]);
        a0.x = fmaf(w0.x, x0.x, a0.x); a0.y = fmaf(w0.y, x0.y, a0.y);
        a0.z = fmaf(w0.z, x0.z, a0.z); a0.w = fmaf(w0.w, x0.w, a0.w);
        a1.x = fmaf(w1.x, x1.x, a1.x); a1.y = fmaf(w1.y, x1.y, a1.y);
        a1.z = fmaf(w1.z, x1.z, a1.z); a1.w = fmaf(w1.w, x1.w, a1.w);
    }
    float s = ((a0.x + a0.y) + (a0.z + a0.w))
            + ((a1.x + a1.y) + (a1.z + a1.w));
#pragma unroll
    for (int o = 16; o > 0; o >>= 1)
        s += __shfl_xor_sync(0xFFFFFFFFu, s, o);
    return s;
}

__global__ __launch_bounds__(256)
void rwkv_mega_kernel(const float* __restrict__ x,
                      const float* __restrict__ state,
                      const float* __restrict__ state_a,
                      const float* __restrict__ state_b,
                      const float* __restrict__ state_p,
                      const float* __restrict__ tmk,
                      const float* __restrict__ tmv,
                      const float* __restrict__ tmr,
                      const float* __restrict__ time_first,
                      const float* __restrict__ time_decay,
                      const float* __restrict__ kw,
                      const float* __restrict__ vw,
                      const float* __restrict__ rw,
                      const float* __restrict__ ow,
                      float* __restrict__ d_out) {
    int b   = blockIdx.x;
    int tid = threadIdx.x;

    // ======================= Phase 1: matvec3 (blocks 0..3071) ==============
    if (b < MV3_BLOCKS) {
        int band   = b / 384;
        int r      = b % 384;
        int rowgrp = r / 6;
        int sub    = r % 6;
        int mat    = sub >> 1;        // 0,0,1,1,2,2
        int kc     = sub & 1;
        const float* W = (mat == 0) ? kw : (mat == 1) ? vw : rw;

        int warp = tid >> 5;
        int lane = tid & 31;
        int row  = band * 512 + rowgrp * 8 + warp;
        int col0 = kc * 2048;

        const float* Wbase = W + (size_t)(band * 512 + rowgrp * 8) * C + col0;

        // Prefetch own 64KB W tile (512 lines, 2 per thread) before the mix
        // wait: keeps DRAM moving during the pipeline-fill window.
        {
            int pr = tid >> 5;                 // 0..7 row within group
            int pl = tid & 31;                 // 0..31
            const char* base = (const char*)(Wbase + (size_t)pr * C);
            l2_prefetch(base + (size_t)pl * 128);
            l2_prefetch(base + (size_t)(pl + 32) * 128);
        }

        // Blocks 0..15 compute the token-shift mix (16*256 = 4096 elements)
        if (b < 16) {
            int i = b * 256 + tid;
            float xi = __ldg(&x[i]);
            float si = __ldg(&state[i]);
            g_x3[i]         = fmaf(xi - si, __ldg(&tmk[i]), si);
            g_x3[C + i]     = fmaf(xi - si, __ldg(&tmv[i]), si);
            g_x3[2 * C + i] = fmaf(xi - si, __ldg(&tmr[i]), si);
            block_signal(&g_mix_ctr);
        }
        block_wait(&g_mix_ctr, 16);

        const float4* Wr = reinterpret_cast<const float4*>(W + (size_t)row * C + col0);
        const float4* xv = reinterpret_cast<const float4*>(g_x3 + mat * C + col0);
        float s = partial_dot<16>(Wr, xv, lane);
        if (lane == 0) g_kvr_p[kc][mat * C + row] = s;

        block_signal(&g_band_ctr[band]);
        return;
    }
    b -= MV3_BLOCKS;

    // ======================= Phase 2: wkv (8 blocks, one per band) ==========
    if (b < WKV_BLOCKS) {
        int kc = b;                       // element band [kc*512, kc*512+512)
        block_wait(&g_band_ctr[kc], 384);

#pragma unroll
        for (int t = 0; t < 2; t++) {
            int i = kc * 512 + t * 256 + tid;

            float kk = g_kvr_p[0][i]         + g_kvr_p[1][i];
            float vv = g_kvr_p[0][C + i]     + g_kvr_p[1][C + i];
            float rr = g_kvr_p[0][2 * C + i] + g_kvr_p[1][2 * C + i];
            float aa = __ldg(&state_a[i]);
            float bb = __ldg(&state_b[i]);
            float pp = __ldg(&state_p[i]);
            float tf = __ldg(&time_first[i]);
            float td = __ldg(&time_decay[i]);

            float rg = 1.0f / (1.0f + expf(-rr));

            float ww = tf + kk;
            float p  = fmaxf(pp, ww);
            float e1 = expf(pp - p);
            float e2 = expf(ww - p);
            float a  = e1 * aa + e2 * vv;
            float bq = e1 * bb + e2;

            float ww2 = pp + td;
            float p2  = fmaxf(ww2, kk);
            float f1  = expf(ww2 - p2);
            float f2  = expf(kk - p2);

            d_out[C + i]     = __ldg(&x[i]);        // new_state
            d_out[2 * C + i] = f1 * aa + f2 * vv;   // new_state_a
            d_out[3 * C + i] = f1 * bb + f2;        // new_state_b
            d_out[4 * C + i] = p2;                  // new_state_p
            g_rwkv[i] = rg * (a / bq);
        }

        __threadfence();
        __syncthreads();
        if (tid == 0) {
            atomicExch(&g_rwkv_flag[kc], 1u);
            *(volatile unsigned*)&g_band_ctr[kc] = 0u;   // consumed; reset for replay
        }
        return;
    }
    b -= WKV_BLOCKS;

    // ======================= Phase 3: ow partial matvec (4096 blocks) =======
    if (b < OW_BLOCKS) {
        int kc     = b / 512;             // ascending with launch order
        int rowgrp = b % 512;
        int warp   = tid >> 5;
        int lane   = tid & 31;
        int row    = rowgrp * 8 + warp;
        int col0   = kc * 512;

        // Prefetch own 16KB ow tile (128 lines) before waiting on the flag.
        if (tid < 128) {
            int pr = tid >> 4;            // 0..7
            int pl = tid & 15;            // 0..15
            const char* base = (const char*)(ow + (size_t)(rowgrp * 8 + pr) * C + col0);
            l2_prefetch(base + (size_t)pl * 128);
        }

        block_wait(&g_rwkv_flag[kc], 1);

        const float4* Wr = reinterpret_cast<const float4*>(ow + (size_t)row * C + col0);
        const float4* xv = reinterpret_cast<const float4*>(g_rwkv + col0);

        float4 a0 = make_float4(0.f, 0.f, 0.f, 0.f);
        float4 a1 = make_float4(0.f, 0.f, 0.f, 0.f);
        {
            float4 w0 = __ldcs(&Wr[lane +  0]);
            float4 w1 = __ldcs(&Wr[lane + 32]);
            float4 w2 = __ldcs(&Wr[lane + 64]);
            float4 w3 = __ldcs(&Wr[lane + 96]);
            float4 x0 = __ldg(&xv[lane +  0]);
            float4 x1 = __ldg(&xv[lane + 32]);
            float4 x2 = __ldg(&xv[lane + 64]);
            float4 x3 = __ldg(&xv[lane + 96]);
            a0.x = fmaf(w0.x, x0.x, a0.x); a0.y = fmaf(w0.y, x0.y, a0.y);
            a0.z = fmaf(w0.z, x0.z, a0.z); a0.w = fmaf(w0.w, x0.w, a0.w);
            a1.x = fmaf(w1.x, x1.x, a1.x); a1.y = fmaf(w1.y, x1.y, a1.y);
            a1.z = fmaf(w1.z, x1.z, a1.z); a1.w = fmaf(w1.w, x1.w, a1.w);
            a0.x = fmaf(w2.x, x2.x, a0.x); a0.y = fmaf(w2.y, x2.y, a0.y);
            a0.z = fmaf(w2.z, x2.z, a0.z); a0.w = fmaf(w2.w, x2.w, a0.w);
            a1.x = fmaf(w3.x, x3.x, a1.x); a1.y = fmaf(w3.y, x3.y, a1.y);
            a1.z = fmaf(w3.z, x3.z, a1.z); a1.w = fmaf(w3.w, x3.w, a1.w);
        }
        float s = ((a0.x + a0.y) + (a0.z + a0.w))
                + ((a1.x + a1.y) + (a1.z + a1.w));
#pragma unroll
        for (int o = 16; o > 0; o >>= 1)
            s += __shfl_xor_sync(0xFFFFFFFFu, s, o);
        if (lane == 0) g_owp[kc][row] = s;

        block_signal(&g_rowred_ctr[rowgrp >> 5]);
        return;
    }
    b -= OW_BLOCKS;

    // ======================= Phase 4: deterministic reduction (16 blocks) ===
    {
        int j = b;                        // rows [j*256, j*256+256)
        block_wait(&g_rowred_ctr[j], 256);

        int row = j * 256 + tid;
        float s = 0.f;
#pragma unroll
        for (int kc = 0; kc < 8; kc++) s += g_owp[kc][row];
        d_out[row] = s;

        __threadfence();
        __syncthreads();
        if (j != 15) {
            if (tid == 0) atomicAdd(&g_red_done, 1u);
        } else if (tid == 0) {
            while (*(volatile unsigned*)&g_red_done < 15u) __nanosleep(128);
            // reset pipeline state for the next graph replay
            *(volatile unsigned*)&g_mix_ctr = 0u;
#pragma unroll
            for (int k = 0; k < NBAND; k++) {
                *(volatile unsigned*)&g_rwkv_flag[k] = 0u;
                *(volatile unsigned*)&g_band_ctr[k]  = 0u;
            }
#pragma unroll
            for (int k = 0; k < RED_BLOCKS; k++)
                *(volatile unsigned*)&g_rowred_ctr[k] = 0u;
            *(volatile unsigned*)&g_red_done = 0u;
            __threadfence();
        }
    }
}

// ---------------------------------------------------------------------------
// Launch. Input order (metadata): x, state, state_a, state_b, state_p,
// time_mix_k, time_mix_v, time_mix_r, time_first, time_decay, kw, vw, rw, ow.
// Output layout: [out | new_state | new_state_a | new_state_b | new_state_p]
// ---------------------------------------------------------------------------
extern "C" void kernel_launch(void* const* d_in, const int* in_sizes, int n_in,
                              void* d_out, int out_size) {
    const float* x   = (const float*)d_in[0];
    const float* st  = (const float*)d_in[1];
    const float* sa  = (const float*)d_in[2];
    const float* sb  = (const float*)d_in[3];
    const float* sp  = (const float*)d_in[4];
    const float* tmk = (const float*)d_in[5];
    const float* tmv = (const float*)d_in[6];
    const float* tmr = (const float*)d_in[7];
    const float* tf  = (const float*)d_in[8];
    const float* td  = (const float*)d_in[9];
    const float* kw  = (const float*)d_in[10];
    const float* vw  = (const float*)d_in[11];
    const float* rw  = (const float*)d_in[12];
    const float* ow  = (const float*)d_in[13];
    float* out = (float*)d_out;

    rwkv_mega_kernel<<<TOTAL_BLOCKS, 256>>>(x, st, sa, sb, sp,
                                            tmk, tmv, tmr, tf, td,
                                            kw, vw, rw, ow, out);
}

// round 9
// speedup vs baseline: 1.2487x; 1.2487x over previous
#include <cuda_runtime.h>
#include <cuda_bf16.h>

#define C 4096

#define NBAND 8
#define MV3_BLOCKS 3072            // 8 bands * 384  (384 = 64 rowgrp * 2 kc * 3 mat)
#define WKV_BLOCKS 8
#define OW_BLOCKS  4096            // 8 kc * 512 rowgrp
#define RED_BLOCKS 16
#define TOTAL_BLOCKS (MV3_BLOCKS + WKV_BLOCKS + OW_BLOCKS + RED_BLOCKS)

// Scratch (allocation-free rule: __device__ globals)
__device__ float g_x3[3 * C];          // xk | xv | xr
__device__ float g_kvr_p[2][3 * C];    // matvec3 partials per K-chunk
__device__ float g_rwkv[C];            // r * wkv
__device__ float g_owp[8][C];          // ow partials per K-chunk

// Pipeline state (zero-init; reset by reducer 15 each launch)
__device__ unsigned g_mix_ctr;
__device__ unsigned g_band_ctr[NBAND];
__device__ unsigned g_rwkv_flag[NBAND];
__device__ unsigned g_rowred_ctr[RED_BLOCKS];
__device__ unsigned g_red_done;

__device__ __forceinline__ void block_signal(unsigned* p) {
    __threadfence();
    __syncthreads();
    if (threadIdx.x == 0) atomicAdd(p, 1u);
}

__device__ __forceinline__ void block_wait(unsigned* p, unsigned target) {
    if (threadIdx.x == 0) {
        while (*(volatile unsigned*)p < target) __nanosleep(128);
    }
    __syncthreads();
    __threadfence();
}

// Partial dot: CHUNK4 float4 per lane. W streamed (__ldcs), x read-only path.
template <int CHUNK4>
__device__ __forceinline__ float partial_dot(const float4* __restrict__ Wr,
                                             const float4* __restrict__ xv,
                                             int lane) {
    float4 a0 = make_float4(0.f, 0.f, 0.f, 0.f);
    float4 a1 = make_float4(0.f, 0.f, 0.f, 0.f);
#pragma unroll
    for (int j = 0; j < CHUNK4; j += 2) {
        float4 w0 = __ldcs(&Wr[lane + (j + 0) * 32]);
        float4 w1 = __ldcs(&Wr[lane + (j + 1) * 32]);
        float4 x0 = __ldg(&xv[lane + (j + 0) * 32]);
        float4 x1 = __ldg(&xv[lane + (j + 1) * 32]);
        a0.x = fmaf(w0.x, x0.x, a0.x); a0.y = fmaf(w0.y, x0.y, a0.y);
        a0.z = fmaf(w0.z, x0.z, a0.z); a0.w = fmaf(w0.w, x0.w, a0.w);
        a1.x = fmaf(w1.x, x1.x, a1.x); a1.y = fmaf(w1.y, x1.y, a1.y);
        a1.z = fmaf(w1.z, x1.z, a1.z); a1.w = fmaf(w1.w, x1.w, a1.w);
    }
    float s = ((a0.x + a0.y) + (a0.z + a0.w))
            + ((a1.x + a1.y) + (a1.z + a1.w));
#pragma unroll
    for (int o = 16; o > 0; o >>= 1)
        s += __shfl_xor_sync(0xFFFFFFFFu, s, o);
    return s;
}

__global__ __launch_bounds__(256)
void rwkv_mega_kernel(const float* __restrict__ x,
                      const float* __restrict__ state,
                      const float* __restrict__ state_a,
                      const float* __restrict__ state_b,
                      const float* __restrict__ state_p,
                      const float* __restrict__ tmk,
                      const float* __restrict__ tmv,
                      const float* __restrict__ tmr,
                      const float* __restrict__ time_first,
                      const float* __restrict__ time_decay,
                      const float* __restrict__ kw,
                      const float* __restrict__ vw,
                      const float* __restrict__ rw,
                      const float* __restrict__ ow,
                      float* __restrict__ d_out) {
    int b   = blockIdx.x;
    int tid = threadIdx.x;

    // ======================= Phase 1: matvec3 (blocks 0..3071) ==============
    if (b < MV3_BLOCKS) {
        int band   = b / 384;
        int r      = b % 384;
        int rowgrp = r / 6;
        int sub    = r % 6;
        int mat    = sub >> 1;        // 0,0,1,1,2,2
        int kc     = sub & 1;
        const float* W = (mat == 0) ? kw : (mat == 1) ? vw : rw;

        int warp = tid >> 5;
        int lane = tid & 31;
        int row  = band * 512 + rowgrp * 8 + warp;
        int col0 = kc * 2048;

        // Blocks 0..15 compute the token-shift mix (16*256 = 4096 elements)
        if (b < 16) {
            int i = b * 256 + tid;
            float xi = __ldg(&x[i]);
            float si = __ldg(&state[i]);
            g_x3[i]         = fmaf(xi - si, __ldg(&tmk[i]), si);
            g_x3[C + i]     = fmaf(xi - si, __ldg(&tmv[i]), si);
            g_x3[2 * C + i] = fmaf(xi - si, __ldg(&tmr[i]), si);
            block_signal(&g_mix_ctr);
        }
        block_wait(&g_mix_ctr, 16);

        const float4* Wr = reinterpret_cast<const float4*>(W + (size_t)row * C + col0);
        const float4* xv = reinterpret_cast<const float4*>(g_x3 + mat * C + col0);
        float s = partial_dot<16>(Wr, xv, lane);
        if (lane == 0) g_kvr_p[kc][mat * C + row] = s;

        block_signal(&g_band_ctr[band]);
        return;
    }
    b -= MV3_BLOCKS;

    // ======================= Phase 2: wkv (8 blocks, one per band) ==========
    if (b < WKV_BLOCKS) {
        int kc = b;                       // element band [kc*512, kc*512+512)
        block_wait(&g_band_ctr[kc], 384);

#pragma unroll
        for (int t = 0; t < 2; t++) {
            int i = kc * 512 + t * 256 + tid;

            float kk = g_kvr_p[0][i]         + g_kvr_p[1][i];
            float vv = g_kvr_p[0][C + i]     + g_kvr_p[1][C + i];
            float rr = g_kvr_p[0][2 * C + i] + g_kvr_p[1][2 * C + i];
            float aa = __ldg(&state_a[i]);
            float bb = __ldg(&state_b[i]);
            float pp = __ldg(&state_p[i]);
            float tf = __ldg(&time_first[i]);
            float td = __ldg(&time_decay[i]);

            float rg = 1.0f / (1.0f + expf(-rr));

            float ww = tf + kk;
            float p  = fmaxf(pp, ww);
            float e1 = expf(pp - p);
            float e2 = expf(ww - p);
            float a  = e1 * aa + e2 * vv;
            float bq = e1 * bb + e2;

            float ww2 = pp + td;
            float p2  = fmaxf(ww2, kk);
            float f1  = expf(ww2 - p2);
            float f2  = expf(kk - p2);

            d_out[C + i]     = __ldg(&x[i]);        // new_state
            d_out[2 * C + i] = f1 * aa + f2 * vv;   // new_state_a
            d_out[3 * C + i] = f1 * bb + f2;        // new_state_b
            d_out[4 * C + i] = p2;                  // new_state_p
            g_rwkv[i] = rg * (a / bq);
        }

        __threadfence();
        __syncthreads();
        if (tid == 0) {
            atomicExch(&g_rwkv_flag[kc], 1u);
            *(volatile unsigned*)&g_band_ctr[kc] = 0u;   // consumed; reset for replay
        }
        return;
    }
    b -= WKV_BLOCKS;

    // ======================= Phase 3: ow partial matvec (4096 blocks) =======
    if (b < OW_BLOCKS) {
        int kc     = b / 512;             // ascending with launch order
        int rowgrp = b % 512;
        int warp   = tid >> 5;
        int lane   = tid & 31;
        int row    = rowgrp * 8 + warp;
        int col0   = kc * 512;

        block_wait(&g_rwkv_flag[kc], 1);

        const float4* Wr = reinterpret_cast<const float4*>(ow + (size_t)row * C + col0);
        const float4* xv = reinterpret_cast<const float4*>(g_rwkv + col0);

        float4 a0 = make_float4(0.f, 0.f, 0.f, 0.f);
        float4 a1 = make_float4(0.f, 0.f, 0.f, 0.f);
        {
            float4 w0 = __ldcs(&Wr[lane +  0]);
            float4 w1 = __ldcs(&Wr[lane + 32]);
            float4 w2 = __ldcs(&Wr[lane + 64]);
            float4 w3 = __ldcs(&Wr[lane + 96]);
            float4 x0 = __ldg(&xv[lane +  0]);
            float4 x1 = __ldg(&xv[lane + 32]);
            float4 x2 = __ldg(&xv[lane + 64]);
            float4 x3 = __ldg(&xv[lane + 96]);
            a0.x = fmaf(w0.x, x0.x, a0.x); a0.y = fmaf(w0.y, x0.y, a0.y);
            a0.z = fmaf(w0.z, x0.z, a0.z); a0.w = fmaf(w0.w, x0.w, a0.w);
            a1.x = fmaf(w1.x, x1.x, a1.x); a1.y = fmaf(w1.y, x1.y, a1.y);
            a1.z = fmaf(w1.z, x1.z, a1.z); a1.w = fmaf(w1.w, x1.w, a1.w);
            a0.x = fmaf(w2.x, x2.x, a0.x); a0.y = fmaf(w2.y, x2.y, a0.y);
            a0.z = fmaf(w2.z, x2.z, a0.z); a0.w = fmaf(w2.w, x2.w, a0.w);
            a1.x = fmaf(w3.x, x3.x, a1.x); a1.y = fmaf(w3.y, x3.y, a1.y);
            a1.z = fmaf(w3.z, x3.z, a1.z); a1.w = fmaf(w3.w, x3.w, a1.w);
        }
        float s = ((a0.x + a0.y) + (a0.z + a0.w))
                + ((a1.x + a1.y) + (a1.z + a1.w));
#pragma unroll
        for (int o = 16; o > 0; o >>= 1)
            s += __shfl_xor_sync(0xFFFFFFFFu, s, o);
        if (lane == 0) g_owp[kc][row] = s;

        block_signal(&g_rowred_ctr[rowgrp >> 5]);
        return;
    }
    b -= OW_BLOCKS;

    // ======================= Phase 4: deterministic reduction (16 blocks) ===
    {
        int j = b;                        // rows [j*256, j*256+256)
        block_wait(&g_rowred_ctr[j], 256);

        int row = j * 256 + tid;
        float s = 0.f;
#pragma unroll
        for (int kc = 0; kc < 8; kc++) s += g_owp[kc][row];
        d_out[row] = s;

        __threadfence();
        __syncthreads();
        if (j != 15) {
            if (tid == 0) atomicAdd(&g_red_done, 1u);
        } else if (tid == 0) {
            while (*(volatile unsigned*)&g_red_done < 15u) __nanosleep(128);
            // reset pipeline state for the next graph replay
            *(volatile unsigned*)&g_mix_ctr = 0u;
#pragma unroll
            for (int k = 0; k < NBAND; k++) {
                *(volatile unsigned*)&g_rwkv_flag[k] = 0u;
                *(volatile unsigned*)&g_band_ctr[k]  = 0u;
            }
#pragma unroll
            for (int k = 0; k < RED_BLOCKS; k++)
                *(volatile unsigned*)&g_rowred_ctr[k] = 0u;
            *(volatile unsigned*)&g_red_done = 0u;
            __threadfence();
        }
    }
}

// ---------------------------------------------------------------------------
// Launch. Input order (metadata): x, state, state_a, state_b, state_p,
// time_mix_k, time_mix_v, time_mix_r, time_first, time_decay, kw, vw, rw, ow.
// Output layout: [out | new_state | new_state_a | new_state_b | new_state_p]
// ---------------------------------------------------------------------------
extern "C" void kernel_launch(void* const* d_in, const int* in_sizes, int n_in,
                              void* d_out, int out_size) {
    const float* x   = (const float*)d_in[0];
    const float* st  = (const float*)d_in[1];
    const float* sa  = (const float*)d_in[2];
    const float* sb  = (const float*)d_in[3];
    const float* sp  = (const float*)d_in[4];
    const float* tmk = (const float*)d_in[5];
    const float* tmv = (const float*)d_in[6];
    const float* tmr = (const float*)d_in[7];
    const float* tf  = (const float*)d_in[8];
    const float* td  = (const float*)d_in[9];
    const float* kw  = (const float*)d_in[10];
    const float* vw  = (const float*)d_in[11];
    const float* rw  = (const float*)d_in[12];
    const float* ow  = (const float*)d_in[13];
    float* out = (float*)d_out;

    rwkv_mega_kernel<<<TOTAL_BLOCKS, 256>>>(x, st, sa, sb, sp,
                                            tmk, tmv, tmr, tf, td,
                                            kw, vw, rw, ow, out);
}

// round 10
// speedup vs baseline: 1.6304x; 1.3057x over previous
#include <cuda_runtime.h>
#include <cuda_bf16.h>

#define C 4096
#define MV_THREADS 256
#define KSPLIT_A 2            // matvec3 K-chunks of 2048
#define KSPLIT_OW 8           // ow K-chunks of 512

// Scratch (allocation-free rule: __device__ globals)
__device__ float g_x3[3 * C];               // xk | xv | xr
__device__ float g_kvr_p[KSPLIT_A][3 * C];  // per-chunk partials (plain stores)
__device__ float g_rwkv[C];                 // r * wkv

// ---------------------------------------------------------------------------
// L2 evict_last load: keeps ow resident in L2 across graph replays while the
// evict-first (__ldcs) weight streams displace each other instead.
// ---------------------------------------------------------------------------
__device__ __forceinline__ float4 ldg_l2_keep(const float4* p, unsigned long long pol) {
    float4 v;
    asm("ld.global.nc.L2::cache_hint.v4.f32 {%0,%1,%2,%3}, [%4], %5;"
        : "=f"(v.x), "=f"(v.y), "=f"(v.z), "=f"(v.w)
        : "l"(p), "l"(pol));
    return v;
}

__device__ __forceinline__ unsigned long long l2_keep_policy() {
    unsigned long long pol;
    asm("createpolicy.fractional.L2::evict_last.b64 %0, 1.0;" : "=l"(pol));
    return pol;
}

// ---------------------------------------------------------------------------
// K1: token-shift mix + new_state copy
// ---------------------------------------------------------------------------
__global__ void mix_kernel(const float* __restrict__ x,
                           const float* __restrict__ state,
                           const float* __restrict__ tmk,
                           const float* __restrict__ tmv,
                           const float* __restrict__ tmr,
                           float* __restrict__ d_out) {
    int i = blockIdx.x * blockDim.x + threadIdx.x;
    if (i >= C) return;
    float xi = x[i];
    float si = state[i];
    g_x3[i]         = fmaf(xi - si, tmk[i], si);
    g_x3[C + i]     = fmaf(xi - si, tmv[i], si);
    g_x3[2 * C + i] = fmaf(xi - si, tmr[i], si);
    d_out[C + i] = xi;     // new_state
}

// Partial dot over CHUNK4 float4s per lane. W streamed evict-first (__ldcs),
// x via read-only path (L1-resident across the block's warps).
template <int CHUNK4>
__device__ __forceinline__ float partial_dot(const float4* __restrict__ Wr,
                                             const float4* __restrict__ xv,
                                             int lane) {
    float4 a0 = make_float4(0.f, 0.f, 0.f, 0.f);
    float4 a1 = make_float4(0.f, 0.f, 0.f, 0.f);
#pragma unroll
    for (int j = 0; j < CHUNK4; j += 2) {
        float4 w0 = __ldcs(&Wr[lane + (j + 0) * 32]);
        float4 w1 = __ldcs(&Wr[lane + (j + 1) * 32]);
        float4 x0 = __ldg(&xv[lane + (j + 0) * 32]);
        float4 x1 = __ldg(&xv[lane + (j + 1) * 32]);
        a0.x = fmaf(w0.x, x0.x, a0.x); a0.y = fmaf(w0.y, x0.y, a0.y);
        a0.z = fmaf(w0.z, x0.z, a0.z); a0.w = fmaf(w0.w, x0.w, a0.w);
        a1.x = fmaf(w1.x, x1.x, a1.x); a1.y = fmaf(w1.y, x1.y, a1.y);
        a1.z = fmaf(w1.z, x1.z, a1.z); a1.w = fmaf(w1.w, x1.w, a1.w);
    }
    float s = ((a0.x + a0.y) + (a0.z + a0.w))
            + ((a1.x + a1.y) + (a1.z + a1.w));
#pragma unroll
    for (int o = 16; o > 0; o >>= 1)
        s += __shfl_xor_sync(0xFFFFFFFFu, s, o);
    return s;
}

// ---------------------------------------------------------------------------
// K2: kw@xk, vw@xv, rw@xr; K split in 2 chunks of 2048.
//     grid = (512, 2, 3) = 3072 blocks. Plain store into g_kvr_p[kc].
// ---------------------------------------------------------------------------
__global__ __launch_bounds__(MV_THREADS)
void matvec3_kernel(const float* __restrict__ kw,
                    const float* __restrict__ vw,
                    const float* __restrict__ rw) {
    int mat  = blockIdx.z;
    int kc   = blockIdx.y;
    const float* W = (mat == 0) ? kw : (mat == 1) ? vw : rw;

    int tid  = threadIdx.x;
    int warp = tid >> 5;
    int lane = tid & 31;
    int row  = blockIdx.x * 8 + warp;
    int col0 = kc * (C / KSPLIT_A);

    const float4* Wr = reinterpret_cast<const float4*>(W + (size_t)row * C + col0);
    const float4* xv = reinterpret_cast<const float4*>(g_x3 + mat * C + col0);

    float s = partial_dot<(C / KSPLIT_A) / 128>(Wr, xv, lane);  // 16 float4/lane
    if (lane == 0) g_kvr_p[kc][mat * C + row] = s;
}

// ---------------------------------------------------------------------------
// K3: wkv elementwise. Sums the partials, writes new_state_a/b/p, g_rwkv,
//     zeroes out[0:C] (atomic target for K4).
// ---------------------------------------------------------------------------
__global__ void wkv_kernel(const float* __restrict__ state_a,
                           const float* __restrict__ state_b,
                           const float* __restrict__ state_p,
                           const float* __restrict__ time_first,
                           const float* __restrict__ time_decay,
                           float* __restrict__ d_out) {
    int i = blockIdx.x * blockDim.x + threadIdx.x;
    if (i >= C) return;

    float kk = 0.f, vv = 0.f, rr = 0.f;
#pragma unroll
    for (int kc = 0; kc < KSPLIT_A; kc++) {
        kk += g_kvr_p[kc][i];
        vv += g_kvr_p[kc][C + i];
        rr += g_kvr_p[kc][2 * C + i];
    }
    float aa = state_a[i];
    float bb = state_b[i];
    float pp = state_p[i];
    float tf = time_first[i];
    float td = time_decay[i];

    float r = 1.0f / (1.0f + expf(-rr));

    float ww = tf + kk;
    float p  = fmaxf(pp, ww);
    float e1 = expf(pp - p);
    float e2 = expf(ww - p);
    float a  = e1 * aa + e2 * vv;
    float b  = e1 * bb + e2;

    float ww2 = pp + td;
    float p2  = fmaxf(ww2, kk);
    float f1  = expf(ww2 - p2);
    float f2  = expf(kk - p2);

    d_out[i]         = 0.0f;               // out accumulator
    d_out[2 * C + i] = f1 * aa + f2 * vv;  // new_state_a
    d_out[3 * C + i] = f1 * bb + f2;       // new_state_b
    d_out[4 * C + i] = p2;                 // new_state_p

    g_rwkv[i] = r * (a / b);
}

// ---------------------------------------------------------------------------
// K4: out += ow @ (r*wkv); grid (512, 8) = 4096 blocks, 512-col chunks.
//     ow loaded with L2 evict_last hint -> stays resident across replays.
// ---------------------------------------------------------------------------
__global__ __launch_bounds__(MV_THREADS)
void matvec_ow_kernel(const float* __restrict__ ow,
                      float* __restrict__ out /* d_out */) {
    int tid  = threadIdx.x;
    int kc   = blockIdx.y;
    int warp = tid >> 5;
    int lane = tid & 31;
    int row  = blockIdx.x * 8 + warp;
    int col0 = kc * (C / KSPLIT_OW);

    const float4* Wr = reinterpret_cast<const float4*>(ow + (size_t)row * C + col0);
    const float4* xv = reinterpret_cast<const float4*>(g_rwkv + col0);

    unsigned long long pol = l2_keep_policy();

    float4 a0 = make_float4(0.f, 0.f, 0.f, 0.f);
    float4 a1 = make_float4(0.f, 0.f, 0.f, 0.f);
    {
        float4 w0 = ldg_l2_keep(&Wr[lane +  0], pol);
        float4 w1 = ldg_l2_keep(&Wr[lane + 32], pol);
        float4 w2 = ldg_l2_keep(&Wr[lane + 64], pol);
        float4 w3 = ldg_l2_keep(&Wr[lane + 96], pol);
        float4 x0 = __ldg(&xv[lane +  0]);
        float4 x1 = __ldg(&xv[lane + 32]);
        float4 x2 = __ldg(&xv[lane + 64]);
        float4 x3 = __ldg(&xv[lane + 96]);
        a0.x = fmaf(w0.x, x0.x, a0.x); a0.y = fmaf(w0.y, x0.y, a0.y);
        a0.z = fmaf(w0.z, x0.z, a0.z); a0.w = fmaf(w0.w, x0.w, a0.w);
        a1.x = fmaf(w1.x, x1.x, a1.x); a1.y = fmaf(w1.y, x1.y, a1.y);
        a1.z = fmaf(w1.z, x1.z, a1.z); a1.w = fmaf(w1.w, x1.w, a1.w);
        a0.x = fmaf(w2.x, x2.x, a0.x); a0.y = fmaf(w2.y, x2.y, a0.y);
        a0.z = fmaf(w2.z, x2.z, a0.z); a0.w = fmaf(w2.w, x2.w, a0.w);
        a1.x = fmaf(w3.x, x3.x, a1.x); a1.y = fmaf(w3.y, x3.y, a1.y);
        a1.z = fmaf(w3.z, x3.z, a1.z); a1.w = fmaf(w3.w, x3.w, a1.w);
    }
    float s = ((a0.x + a0.y) + (a0.z + a0.w))
            + ((a1.x + a1.y) + (a1.z + a1.w));
#pragma unroll
    for (int o = 16; o > 0; o >>= 1)
        s += __shfl_xor_sync(0xFFFFFFFFu, s, o);
    if (lane == 0) atomicAdd(&out[row], s);
}

// ---------------------------------------------------------------------------
// Launch. Input order (metadata): x, state, state_a, state_b, state_p,
// time_mix_k, time_mix_v, time_mix_r, time_first, time_decay, kw, vw, rw, ow.
// Output layout: [out | new_state | new_state_a | new_state_b | new_state_p]
// ---------------------------------------------------------------------------
extern "C" void kernel_launch(void* const* d_in, const int* in_sizes, int n_in,
                              void* d_out, int out_size) {
    const float* x   = (const float*)d_in[0];
    const float* st  = (const float*)d_in[1];
    const float* sa  = (const float*)d_in[2];
    const float* sb  = (const float*)d_in[3];
    const float* sp  = (const float*)d_in[4];
    const float* tmk = (const float*)d_in[5];
    const float* tmv = (const float*)d_in[6];
    const float* tmr = (const float*)d_in[7];
    const float* tf  = (const float*)d_in[8];
    const float* td  = (const float*)d_in[9];
    const float* kw  = (const float*)d_in[10];
    const float* vw  = (const float*)d_in[11];
    const float* rw  = (const float*)d_in[12];
    const float* ow  = (const float*)d_in[13];
    float* out = (float*)d_out;

    mix_kernel<<<C / 256, 256>>>(x, st, tmk, tmv, tmr, out);

    dim3 g2(C / 8, KSPLIT_A, 3);          // (512, 2, 3) = 3072 blocks
    matvec3_kernel<<<g2, MV_THREADS>>>(kw, vw, rw);

    wkv_kernel<<<C / 256, 256>>>(sa, sb, sp, tf, td, out);

    dim3 g4(C / 8, KSPLIT_OW);            // (512, 8) = 4096 blocks
    matvec_ow_kernel<<<g4, MV_THREADS>>>(ow, out);
}